// round 1
// baseline (speedup 1.0000x reference)
#include <cuda_runtime.h>

#define B_DIM 2
#define T_DIM 2048
#define C_DIM 1024
#define H_DIM 16
#define D_DIM 64
#define BT    (B_DIM * T_DIM)     // 4096
#define N3C   (3 * C_DIM)         // 3072
#define SROW  68                  // smem row stride (64 + 4 pad, keeps 16B alignment)

// Scratch: Q/K/V in [B,H,T,D] layout (16 MB each). __device__ globals per alloc rules.
__device__ float g_Q[B_DIM * H_DIM * T_DIM * D_DIM];
__device__ float g_K[B_DIM * H_DIM * T_DIM * D_DIM];
__device__ float g_V[B_DIM * H_DIM * T_DIM * D_DIM];

// ---------------------------------------------------------------------------
// Kernel 1: qkv = x @ W^T + b, scattered directly into g_Q/g_K/g_V [B,H,T,D]
// Block tile 64(M) x 64(N), K-tile 16. 256 threads, 4x4 per thread.
// Smem tiles stored [k][m] / [k][n] so inner loop reads are float4, conflict-free.
// ---------------------------------------------------------------------------
__global__ __launch_bounds__(256) void qkv_gemm(
    const float* __restrict__ x, const float* __restrict__ Wm,
    const float* __restrict__ bias)
{
    __shared__ float As[16][SROW];
    __shared__ float Bs[16][SROW];

    const int tid  = threadIdx.y * 16 + threadIdx.x;
    const int m0   = blockIdx.y * 64;
    const int n0   = blockIdx.x * 64;
    const int lrow = tid >> 2;            // 0..63
    const int lk4  = (tid & 3) << 2;      // 0,4,8,12
    const int ty4  = threadIdx.y << 2;
    const int tx4  = threadIdx.x << 2;

    float acc[4][4];
#pragma unroll
    for (int i = 0; i < 4; i++)
#pragma unroll
        for (int j = 0; j < 4; j++) acc[i][j] = 0.f;

    const float* xp = x  + (size_t)(m0 + lrow) * C_DIM + lk4;
    const float* wp = Wm + (size_t)(n0 + lrow) * C_DIM + lk4;

    for (int k0 = 0; k0 < C_DIM; k0 += 16) {
        float4 av = *(const float4*)(xp + k0);
        float4 bv = *(const float4*)(wp + k0);
        __syncthreads();
        As[lk4 + 0][lrow] = av.x; As[lk4 + 1][lrow] = av.y;
        As[lk4 + 2][lrow] = av.z; As[lk4 + 3][lrow] = av.w;
        Bs[lk4 + 0][lrow] = bv.x; Bs[lk4 + 1][lrow] = bv.y;
        Bs[lk4 + 2][lrow] = bv.z; Bs[lk4 + 3][lrow] = bv.w;
        __syncthreads();
#pragma unroll
        for (int kk = 0; kk < 16; kk++) {
            float4 a = *(const float4*)&As[kk][ty4];
            float4 b = *(const float4*)&Bs[kk][tx4];
            float aa[4] = {a.x, a.y, a.z, a.w};
            float bb[4] = {b.x, b.y, b.z, b.w};
#pragma unroll
            for (int i = 0; i < 4; i++)
#pragma unroll
                for (int j = 0; j < 4; j++)
                    acc[i][j] = fmaf(aa[i], bb[j], acc[i][j]);
        }
    }

    // Scatter to Q/K/V [B,H,T,D] with bias add.
#pragma unroll
    for (int j = 0; j < 4; j++) {
        const int n   = n0 + tx4 + j;
        const float bv = bias[n];
        const int sel = n >> 10;            // 0=q,1=k,2=v
        const int c   = n & (C_DIM - 1);
        const int h   = c >> 6;
        const int d   = c & (D_DIM - 1);
        float* dst = (sel == 0) ? g_Q : (sel == 1) ? g_K : g_V;
#pragma unroll
        for (int i = 0; i < 4; i++) {
            const int m  = m0 + ty4 + i;
            const int bi = m >> 11;
            const int t  = m & (T_DIM - 1);
            dst[(((size_t)bi * H_DIM + h) * T_DIM + t) * D_DIM + d] = acc[i][j] + bv;
        }
    }
}

// ---------------------------------------------------------------------------
// Kernel 2: streaming causal ReLU attention.
// One CTA = one 64-query tile of one (b,h). Loops key tiles jt <= it,
// skipping the upper triangle entirely. Y accumulated in registers.
//   S = relu(Q K^T / 8), masked on the diagonal tile; Y += S V.
// ---------------------------------------------------------------------------
__global__ __launch_bounds__(256) void attn_kernel(float* __restrict__ out)
{
    extern __shared__ float sm[];
    float* Qt = sm;                  // [d][i]  transposed Q tile
    float* Kt = Qt + 64 * SROW;      // [d][j]  transposed K tile
    float* Vs = Kt + 64 * SROW;      // [j][d]  V tile, natural
    float* Ss = Vs + 64 * SROW;      // [i][j]  score tile

    const int it  = blockIdx.x;      // query tile 0..31
    const int bh  = blockIdx.y;      // b*16+h, 0..31
    const int tid = threadIdx.y * 16 + threadIdx.x;
    const int lrow = tid >> 2;
    const int lc4  = (tid & 3) << 2;
    const int ty4  = threadIdx.y << 2;
    const int tx4  = threadIdx.x << 2;

    const float* Qg = g_Q + ((size_t)bh * T_DIM + it * 64) * D_DIM;
    const float* Kb = g_K + (size_t)bh * T_DIM * D_DIM;
    const float* Vb = g_V + (size_t)bh * T_DIM * D_DIM;

    // Load Q tile once, transposed into smem.
#pragma unroll
    for (int q = 0; q < 4; q++) {
        const int cc = lc4 + q * 16;
        float4 v = *(const float4*)&Qg[lrow * D_DIM + cc];
        Qt[(cc + 0) * SROW + lrow] = v.x;
        Qt[(cc + 1) * SROW + lrow] = v.y;
        Qt[(cc + 2) * SROW + lrow] = v.z;
        Qt[(cc + 3) * SROW + lrow] = v.w;
    }

    float acc[4][4];
#pragma unroll
    for (int i = 0; i < 4; i++)
#pragma unroll
        for (int j = 0; j < 4; j++) acc[i][j] = 0.f;

    for (int jt = 0; jt <= it; jt++) {
        const float* Kg = Kb + (size_t)jt * 64 * D_DIM;
        const float* Vg = Vb + (size_t)jt * 64 * D_DIM;

        __syncthreads();   // previous iter done reading Kt/Vs/Ss (also orders Q stores)
#pragma unroll
        for (int q = 0; q < 4; q++) {
            const int cc = lc4 + q * 16;
            float4 kv = *(const float4*)&Kg[lrow * D_DIM + cc];
            Kt[(cc + 0) * SROW + lrow] = kv.x;
            Kt[(cc + 1) * SROW + lrow] = kv.y;
            Kt[(cc + 2) * SROW + lrow] = kv.z;
            Kt[(cc + 3) * SROW + lrow] = kv.w;
            float4 vv = *(const float4*)&Vg[lrow * D_DIM + cc];
            *(float4*)&Vs[lrow * SROW + cc] = vv;
        }
        __syncthreads();

        // S = Q K^T
        float s[4][4];
#pragma unroll
        for (int i = 0; i < 4; i++)
#pragma unroll
            for (int j = 0; j < 4; j++) s[i][j] = 0.f;
#pragma unroll 8
        for (int dd = 0; dd < 64; dd++) {
            float4 a = *(const float4*)&Qt[dd * SROW + ty4];
            float4 b = *(const float4*)&Kt[dd * SROW + tx4];
            float aa[4] = {a.x, a.y, a.z, a.w};
            float bb[4] = {b.x, b.y, b.z, b.w};
#pragma unroll
            for (int i = 0; i < 4; i++)
#pragma unroll
                for (int j = 0; j < 4; j++)
                    s[i][j] = fmaf(aa[i], bb[j], s[i][j]);
        }

        // scale + ReLU + causal mask (diagonal tile only), write to smem
        const bool diag = (jt == it);
#pragma unroll
        for (int i = 0; i < 4; i++) {
            float r[4];
#pragma unroll
            for (int j = 0; j < 4; j++) {
                float v = fmaxf(s[i][j] * 0.125f, 0.f);
                if (diag && (tx4 + j > ty4 + i)) v = 0.f;
                r[j] = v;
            }
            float4 rv = make_float4(r[0], r[1], r[2], r[3]);
            *(float4*)&Ss[(ty4 + i) * SROW + tx4] = rv;
        }
        __syncthreads();

        // Y += S V
#pragma unroll 8
        for (int jj = 0; jj < 64; jj++) {
            float4 b = *(const float4*)&Vs[jj * SROW + tx4];
            float bb[4] = {b.x, b.y, b.z, b.w};
#pragma unroll
            for (int i = 0; i < 4; i++) {
                const float a = Ss[(ty4 + i) * SROW + jj];
#pragma unroll
                for (int j = 0; j < 4; j++)
                    acc[i][j] = fmaf(a, bb[j], acc[i][j]);
            }
        }
    }

    // Write out: out[b][t][h*64 + d]
    const int bi = bh >> 4;
    const int h  = bh & 15;
#pragma unroll
    for (int i = 0; i < 4; i++) {
        const int t = it * 64 + ty4 + i;
        float4 rv = make_float4(acc[i][0], acc[i][1], acc[i][2], acc[i][3]);
        *(float4*)&out[((size_t)bi * T_DIM + t) * C_DIM + h * D_DIM + tx4] = rv;
    }
}

// ---------------------------------------------------------------------------
extern "C" void kernel_launch(void* const* d_in, const int* in_sizes, int n_in,
                              void* d_out, int out_size)
{
    const float* x  = (const float*)d_in[0];
    const float* W  = (const float*)d_in[1];
    const float* b  = (const float*)d_in[2];
    float* out = (float*)d_out;

    dim3 blk(16, 16);

    dim3 g1(N3C / 64, BT / 64);   // (48, 64)
    qkv_gemm<<<g1, blk>>>(x, W, b);

    const int attn_smem = 4 * 64 * SROW * (int)sizeof(float);   // 69,632 B
    cudaFuncSetAttribute(attn_kernel,
                         cudaFuncAttributeMaxDynamicSharedMemorySize, attn_smem);
    dim3 g2(T_DIM / 64, B_DIM * H_DIM);  // (32, 32)
    attn_kernel<<<g2, blk, attn_smem>>>(out);
}

// round 11
// speedup vs baseline: 1.7312x; 1.7312x over previous
#include <cuda_runtime.h>
#include <cuda_bf16.h>
#include <cstdint>

#define B_DIM 2
#define T_DIM 2048
#define C_DIM 1024
#define H_DIM 16
#define D_DIM 64
#define BT    (B_DIM * T_DIM)     // 4096
#define N3C   (3 * C_DIM)         // 3072

// fp32 scratch (GEMM out -> attention in)
__device__ float g_Q[B_DIM * H_DIM * T_DIM * D_DIM];
__device__ float g_K[B_DIM * H_DIM * T_DIM * D_DIM];
__device__ float g_V[B_DIM * H_DIM * T_DIM * D_DIM];

// split-bf16 GEMM operands
__device__ __align__(16) __nv_bfloat16 g_xhi[BT * C_DIM];
__device__ __align__(16) __nv_bfloat16 g_xlo[BT * C_DIM];
__device__ __align__(16) __nv_bfloat16 g_whi[N3C * C_DIM];
__device__ __align__(16) __nv_bfloat16 g_wlo[N3C * C_DIM];

// ---------------------------------------------------------------------------
// mma.sync m16n8k16 bf16, fp32 accumulate (baseline PTX, works on compute_103)
// ---------------------------------------------------------------------------
__device__ __forceinline__ void mma_bf16(float d[4], const uint32_t a[4],
                                         uint32_t b0, uint32_t b1) {
    asm volatile(
        "mma.sync.aligned.m16n8k16.row.col.f32.bf16.bf16.f32 "
        "{%0,%1,%2,%3}, {%4,%5,%6,%7}, {%8,%9}, {%0,%1,%2,%3};\n"
        : "+f"(d[0]), "+f"(d[1]), "+f"(d[2]), "+f"(d[3])
        : "r"(a[0]), "r"(a[1]), "r"(a[2]), "r"(a[3]), "r"(b0), "r"(b1));
}

// split one fp32 into bf16 hi + bf16 lo
__device__ __forceinline__ void split1(float v, __nv_bfloat16& h, __nv_bfloat16& l) {
    h = __float2bfloat16(v);
    l = __float2bfloat16(v - __bfloat162float(h));
}

// split a pair (a=low lane, b=high lane) into packed bf16x2 hi / lo regs
__device__ __forceinline__ void split2(float a, float b, uint32_t& hi, uint32_t& lo) {
    __nv_bfloat162 h = __floats2bfloat162_rn(a, b);     // .x = a (low)
    float ra = a - __bfloat162float(h.x);
    float rb = b - __bfloat162float(h.y);
    __nv_bfloat162 l = __floats2bfloat162_rn(ra, rb);
    hi = *reinterpret_cast<uint32_t*>(&h);
    lo = *reinterpret_cast<uint32_t*>(&l);
}

// ---------------------------------------------------------------------------
// Kernel 0: split x and W into bf16 hi/lo pairs
// ---------------------------------------------------------------------------
__global__ __launch_bounds__(256) void split_convert(
    const float4* __restrict__ x4, const float4* __restrict__ w4)
{
    const int NX4 = BT * C_DIM / 4;
    const int NW4 = N3C * C_DIM / 4;
    for (int i = blockIdx.x * blockDim.x + threadIdx.x; i < NX4 + NW4;
         i += gridDim.x * blockDim.x) {
        float4 v;
        uint32_t *ph, *pl;
        if (i < NX4) {
            v  = x4[i];
            ph = (uint32_t*)g_xhi + (size_t)i * 2;
            pl = (uint32_t*)g_xlo + (size_t)i * 2;
        } else {
            int j = i - NX4;
            v  = w4[j];
            ph = (uint32_t*)g_whi + (size_t)j * 2;
            pl = (uint32_t*)g_wlo + (size_t)j * 2;
        }
        uint32_t h0, l0, h1, l1;
        split2(v.x, v.y, h0, l0);
        split2(v.z, v.w, h1, l1);
        ph[0] = h0; ph[1] = h1;
        pl[0] = l0; pl[1] = l1;
    }
}

// ---------------------------------------------------------------------------
// Kernel 1: qkv = x @ W^T + b via mma.sync, split-bf16 (3 products).
// CTA 128x128, 8 warps as 4(M) x 2(N) -> warp tile 32x64. K-chunk 32,
// double-buffered smem, row stride 40 bf16 (conflict-free fragment loads).
// ---------------------------------------------------------------------------
#define GK     32
#define GPAD   40
#define GTILE  (128 * GPAD)          // elems per array per buffer
#define NCHUNK (C_DIM / GK)          // 32

__global__ __launch_bounds__(256) void qkv_gemm_mma(const float* __restrict__ bias)
{
    extern __shared__ __nv_bfloat16 smg[];
    // layout: [buf(2)][arr(4: Ah, Al, Bh, Bl)][128][GPAD]

    const int tid  = threadIdx.x;
    const int wid  = tid >> 5;
    const int lane = tid & 31;
    const int wm   = wid & 3;        // warp m index (0..3)
    const int wn   = wid >> 2;       // warp n index (0..1)
    const int g    = lane >> 2;      // groupID
    const int tg   = lane & 3;       // thread-in-group
    const int m0   = blockIdx.y * 128;
    const int n0   = blockIdx.x * 128;

    const int row  = tid >> 1;       // 0..127 (staging row)
    const int half = tid & 1;        // k half (0/1)

    const __nv_bfloat16* src[4] = {
        g_xhi + (size_t)(m0 + row) * C_DIM + half * 16,
        g_xlo + (size_t)(m0 + row) * C_DIM + half * 16,
        g_whi + (size_t)(n0 + row) * C_DIM + half * 16,
        g_wlo + (size_t)(n0 + row) * C_DIM + half * 16
    };

    float acc[2][8][4];
#pragma unroll
    for (int mi = 0; mi < 2; mi++)
#pragma unroll
        for (int ni = 0; ni < 8; ni++)
#pragma unroll
            for (int r = 0; r < 4; r++) acc[mi][ni][r] = 0.f;

    uint4 stage[4][2];
#pragma unroll
    for (int t = 0; t < 4; t++)
#pragma unroll
        for (int i = 0; i < 2; i++)
            stage[t][i] = *(const uint4*)(src[t] + i * 8);

    const int sts_off = row * GPAD + half * 16;
#pragma unroll
    for (int t = 0; t < 4; t++) {
        *(uint4*)&smg[(size_t)t * GTILE + sts_off + 0] = stage[t][0];
        *(uint4*)&smg[(size_t)t * GTILE + sts_off + 8] = stage[t][1];
    }
    __syncthreads();

    for (int kc = 0; kc < NCHUNK; kc++) {
        const int buf = kc & 1;
        if (kc + 1 < NCHUNK) {
#pragma unroll
            for (int t = 0; t < 4; t++)
#pragma unroll
                for (int i = 0; i < 2; i++)
                    stage[t][i] = *(const uint4*)(src[t] + (kc + 1) * GK + i * 8);
        }

        const __nv_bfloat16* Ah = smg + (size_t)(buf * 4 + 0) * GTILE;
        const __nv_bfloat16* Al = smg + (size_t)(buf * 4 + 1) * GTILE;
        const __nv_bfloat16* Bh = smg + (size_t)(buf * 4 + 2) * GTILE;
        const __nv_bfloat16* Bl = smg + (size_t)(buf * 4 + 3) * GTILE;

#pragma unroll
        for (int ks = 0; ks < 2; ks++) {
            const int k0 = ks * 16;
            uint32_t ah[2][4], al[2][4];
#pragma unroll
            for (int mi = 0; mi < 2; mi++) {
                const int r0 = wm * 32 + mi * 16 + g;
                ah[mi][0] = *(const uint32_t*)&Ah[r0 * GPAD + k0 + 2 * tg];
                ah[mi][1] = *(const uint32_t*)&Ah[(r0 + 8) * GPAD + k0 + 2 * tg];
                ah[mi][2] = *(const uint32_t*)&Ah[r0 * GPAD + k0 + 2 * tg + 8];
                ah[mi][3] = *(const uint32_t*)&Ah[(r0 + 8) * GPAD + k0 + 2 * tg + 8];
                al[mi][0] = *(const uint32_t*)&Al[r0 * GPAD + k0 + 2 * tg];
                al[mi][1] = *(const uint32_t*)&Al[(r0 + 8) * GPAD + k0 + 2 * tg];
                al[mi][2] = *(const uint32_t*)&Al[r0 * GPAD + k0 + 2 * tg + 8];
                al[mi][3] = *(const uint32_t*)&Al[(r0 + 8) * GPAD + k0 + 2 * tg + 8];
            }
#pragma unroll
            for (int ni = 0; ni < 8; ni++) {
                const int n = wn * 64 + ni * 8 + g;
                uint32_t bh0 = *(const uint32_t*)&Bh[n * GPAD + k0 + 2 * tg];
                uint32_t bh1 = *(const uint32_t*)&Bh[n * GPAD + k0 + 2 * tg + 8];
                uint32_t bl0 = *(const uint32_t*)&Bl[n * GPAD + k0 + 2 * tg];
                uint32_t bl1 = *(const uint32_t*)&Bl[n * GPAD + k0 + 2 * tg + 8];
#pragma unroll
                for (int mi = 0; mi < 2; mi++) {
                    mma_bf16(acc[mi][ni], ah[mi], bh0, bh1);
                    mma_bf16(acc[mi][ni], al[mi], bh0, bh1);
                    mma_bf16(acc[mi][ni], ah[mi], bl0, bl1);
                }
            }
        }

        if (kc + 1 < NCHUNK) {
            const int nb = buf ^ 1;
#pragma unroll
            for (int t = 0; t < 4; t++) {
                *(uint4*)&smg[(size_t)(nb * 4 + t) * GTILE + sts_off + 0] = stage[t][0];
                *(uint4*)&smg[(size_t)(nb * 4 + t) * GTILE + sts_off + 8] = stage[t][1];
            }
        }
        __syncthreads();
    }

    // epilogue: fp32 + bias, scatter to g_Q/g_K/g_V in [B,H,T,D]
#pragma unroll
    for (int ni = 0; ni < 8; ni++) {
        const int n_glob = n0 + wn * 64 + ni * 8 + 2 * tg;
        const int sel = n_glob >> 10;
        const int c   = n_glob & (C_DIM - 1);
        const int h   = c >> 6;
        const int d   = c & (D_DIM - 1);
        float* dst = (sel == 0) ? g_Q : (sel == 1) ? g_K : g_V;
        const float2 bv = *(const float2*)&bias[n_glob];
#pragma unroll
        for (int mi = 0; mi < 2; mi++) {
            const int rb = m0 + wm * 32 + mi * 16 + g;
#pragma unroll
            for (int r2 = 0; r2 < 2; r2++) {
                const int m  = rb + r2 * 8;
                const int bi = m >> 11;
                const int t  = m & (T_DIM - 1);
                float2 o;
                o.x = acc[mi][ni][2 * r2 + 0] + bv.x;
                o.y = acc[mi][ni][2 * r2 + 1] + bv.y;
                *(float2*)&dst[(((size_t)(bi * H_DIM + h) * T_DIM) + t) * D_DIM + d] = o;
            }
        }
    }
}

// ---------------------------------------------------------------------------
// Kernel 2: causal ReLU attention via mma.sync, split-bf16.
// CTA = 64 queries of one (b,h); 4 warps, each warp owns 16 query rows.
// Tiles are 64 columns wide -> row stride APAD = 72 (64 + 8 pad).
// 6 arrays * 64*72 bf16 = 55,296 B -> dynamic shared memory.
// ---------------------------------------------------------------------------
#define APAD 72
#define ATILE (64 * APAD)

__global__ __launch_bounds__(128) void attn_mma(float* __restrict__ out)
{
    extern __shared__ __nv_bfloat16 sma[];
    __nv_bfloat16* sQh = sma;
    __nv_bfloat16* sQl = sQh + ATILE;
    __nv_bfloat16* sKh = sQl + ATILE;
    __nv_bfloat16* sKl = sKh + ATILE;
    __nv_bfloat16* sVh = sKl + ATILE;
    __nv_bfloat16* sVl = sVh + ATILE;

    const int tid  = threadIdx.x;
    const int wid  = tid >> 5;
    const int lane = tid & 31;
    const int g    = lane >> 2;
    const int tg   = lane & 3;
    const int it   = (T_DIM / 64 - 1) - blockIdx.x;   // big tiles first
    const int bh   = blockIdx.y;

    const int row = tid >> 1;          // 0..63
    const int cb  = (tid & 1) * 32;    // column half

    // ---- load + split Q tile ----
    {
        const float* Qg = g_Q + ((size_t)bh * T_DIM + it * 64 + row) * D_DIM + cb;
#pragma unroll
        for (int c = 0; c < 8; c++) {
            float4 v = *(const float4*)&Qg[4 * c];
            uint32_t h0, l0, h1, l1;
            split2(v.x, v.y, h0, l0);
            split2(v.z, v.w, h1, l1);
            const int o = row * APAD + cb + 4 * c;
            *(uint2*)&sQh[o] = make_uint2(h0, h1);
            *(uint2*)&sQl[o] = make_uint2(l0, l1);
        }
    }
    __syncthreads();

    // ---- Q fragments (held in regs for the whole CTA lifetime) ----
    uint32_t qh[4][4], ql[4][4];
    {
        const int r0 = wid * 16 + g;
#pragma unroll
        for (int kd = 0; kd < 4; kd++) {
            const int k0 = kd * 16;
            qh[kd][0] = *(const uint32_t*)&sQh[r0 * APAD + k0 + 2 * tg];
            qh[kd][1] = *(const uint32_t*)&sQh[(r0 + 8) * APAD + k0 + 2 * tg];
            qh[kd][2] = *(const uint32_t*)&sQh[r0 * APAD + k0 + 2 * tg + 8];
            qh[kd][3] = *(const uint32_t*)&sQh[(r0 + 8) * APAD + k0 + 2 * tg + 8];
            ql[kd][0] = *(const uint32_t*)&sQl[r0 * APAD + k0 + 2 * tg];
            ql[kd][1] = *(const uint32_t*)&sQl[(r0 + 8) * APAD + k0 + 2 * tg];
            ql[kd][2] = *(const uint32_t*)&sQl[r0 * APAD + k0 + 2 * tg + 8];
            ql[kd][3] = *(const uint32_t*)&sQl[(r0 + 8) * APAD + k0 + 2 * tg + 8];
        }
    }

    float y[8][4];
#pragma unroll
    for (int nd = 0; nd < 8; nd++)
#pragma unroll
        for (int r = 0; r < 4; r++) y[nd][r] = 0.f;

    for (int jt = 0; jt <= it; jt++) {
        __syncthreads();   // previous iteration done reading sK/sV

        // ---- load + split K (natural) and V (transposed) tiles ----
        {
            const float* Kg = g_K + ((size_t)bh * T_DIM + jt * 64 + row) * D_DIM + cb;
            const float* Vg = g_V + ((size_t)bh * T_DIM + jt * 64 + row) * D_DIM + cb;
#pragma unroll
            for (int c = 0; c < 8; c++) {
                float4 kv = *(const float4*)&Kg[4 * c];
                uint32_t h0, l0, h1, l1;
                split2(kv.x, kv.y, h0, l0);
                split2(kv.z, kv.w, h1, l1);
                const int o = row * APAD + cb + 4 * c;
                *(uint2*)&sKh[o] = make_uint2(h0, h1);
                *(uint2*)&sKl[o] = make_uint2(l0, l1);

                float4 vv = *(const float4*)&Vg[4 * c];
                const int d0 = cb + 4 * c;
                __nv_bfloat16 vh, vl;
                split1(vv.x, vh, vl); sVh[(d0 + 0) * APAD + row] = vh; sVl[(d0 + 0) * APAD + row] = vl;
                split1(vv.y, vh, vl); sVh[(d0 + 1) * APAD + row] = vh; sVl[(d0 + 1) * APAD + row] = vl;
                split1(vv.z, vh, vl); sVh[(d0 + 2) * APAD + row] = vh; sVl[(d0 + 2) * APAD + row] = vl;
                split1(vv.w, vh, vl); sVh[(d0 + 3) * APAD + row] = vh; sVl[(d0 + 3) * APAD + row] = vl;
            }
        }
        __syncthreads();

        // ---- S = Q K^T ----
        float s[8][4];
#pragma unroll
        for (int ni = 0; ni < 8; ni++)
#pragma unroll
            for (int r = 0; r < 4; r++) s[ni][r] = 0.f;

#pragma unroll
        for (int kd = 0; kd < 4; kd++) {
            const int k0 = kd * 16;
#pragma unroll
            for (int ni = 0; ni < 8; ni++) {
                const int n = ni * 8 + g;
                uint32_t bh0 = *(const uint32_t*)&sKh[n * APAD + k0 + 2 * tg];
                uint32_t bh1 = *(const uint32_t*)&sKh[n * APAD + k0 + 2 * tg + 8];
                uint32_t bl0 = *(const uint32_t*)&sKl[n * APAD + k0 + 2 * tg];
                uint32_t bl1 = *(const uint32_t*)&sKl[n * APAD + k0 + 2 * tg + 8];
                mma_bf16(s[ni], qh[kd], bh0, bh1);
                mma_bf16(s[ni], ql[kd], bh0, bh1);
                mma_bf16(s[ni], qh[kd], bl0, bl1);
            }
        }

        // ---- scale + ReLU + causal mask, then split into A fragments ----
        const bool diag = (jt == it);
#pragma unroll
        for (int ni = 0; ni < 8; ni++) {
#pragma unroll
            for (int r = 0; r < 4; r++) {
                float v = fmaxf(s[ni][r] * 0.125f, 0.f);
                if (diag) {
                    const int ri = wid * 16 + g + (r >> 1) * 8;
                    const int cj = ni * 8 + 2 * tg + (r & 1);
                    if (cj > ri) v = 0.f;
                }
                s[ni][r] = v;
            }
        }

        uint32_t ash[4][4], asl[4][4];
#pragma unroll
        for (int kj = 0; kj < 4; kj++) {
            split2(s[2 * kj][0],     s[2 * kj][1],     ash[kj][0], asl[kj][0]);
            split2(s[2 * kj][2],     s[2 * kj][3],     ash[kj][1], asl[kj][1]);
            split2(s[2 * kj + 1][0], s[2 * kj + 1][1], ash[kj][2], asl[kj][2]);
            split2(s[2 * kj + 1][2], s[2 * kj + 1][3], ash[kj][3], asl[kj][3]);
        }

        // ---- Y += S V ----
#pragma unroll
        for (int kj = 0; kj < 4; kj++) {
            const int k0 = kj * 16;
#pragma unroll
            for (int nd = 0; nd < 8; nd++) {
                const int n = nd * 8 + g;
                uint32_t bh0 = *(const uint32_t*)&sVh[n * APAD + k0 + 2 * tg];
                uint32_t bh1 = *(const uint32_t*)&sVh[n * APAD + k0 + 2 * tg + 8];
                uint32_t bl0 = *(const uint32_t*)&sVl[n * APAD + k0 + 2 * tg];
                uint32_t bl1 = *(const uint32_t*)&sVl[n * APAD + k0 + 2 * tg + 8];
                mma_bf16(y[nd], ash[kj], bh0, bh1);
                mma_bf16(y[nd], asl[kj], bh0, bh1);
                mma_bf16(y[nd], ash[kj], bl0, bl1);
            }
        }
    }

    // ---- epilogue: out[b][t][h*64 + d] ----
    const int bi = bh >> 4;
    const int h  = bh & 15;
#pragma unroll
    for (int nd = 0; nd < 8; nd++) {
        const int d = h * D_DIM + nd * 8 + 2 * tg;
#pragma unroll
        for (int r2 = 0; r2 < 2; r2++) {
            const int t = it * 64 + wid * 16 + g + r2 * 8;
            float2 o;
            o.x = y[nd][2 * r2 + 0];
            o.y = y[nd][2 * r2 + 1];
            *(float2*)&out[((size_t)bi * T_DIM + t) * C_DIM + d] = o;
        }
    }
}

// ---------------------------------------------------------------------------
extern "C" void kernel_launch(void* const* d_in, const int* in_sizes, int n_in,
                              void* d_out, int out_size)
{
    const float* x  = (const float*)d_in[0];
    const float* W  = (const float*)d_in[1];
    const float* b  = (const float*)d_in[2];
    float* out = (float*)d_out;

    split_convert<<<2048, 256>>>((const float4*)x, (const float4*)W);

    const int gemm_smem = 2 * 4 * GTILE * (int)sizeof(__nv_bfloat16);  // 81920
    cudaFuncSetAttribute(qkv_gemm_mma,
                         cudaFuncAttributeMaxDynamicSharedMemorySize, gemm_smem);
    dim3 g1(N3C / 128, BT / 128);   // (24, 32)
    qkv_gemm_mma<<<g1, 256, gemm_smem>>>(b);

    const int attn_smem = 6 * ATILE * (int)sizeof(__nv_bfloat16);      // 55296
    cudaFuncSetAttribute(attn_mma,
                         cudaFuncAttributeMaxDynamicSharedMemorySize, attn_smem);
    dim3 g2(T_DIM / 64, B_DIM * H_DIM);   // (32, 32)
    attn_mma<<<g2, 128, attn_smem>>>(out);
}